// round 4
// baseline (speedup 1.0000x reference)
#include <cuda_runtime.h>
#include <cuda_bf16.h>
#include <cstdint>
#include <math.h>

// ---------------- device scratch (no allocations allowed) -------------------
__device__ float g_T[512 * 512];    // fixed sinusoidal table, rows 0..511
__device__ float g_Wt[96 * 512];    // conv weight transposed: [kk = tap*32+c][d]
__device__ int   g_cnt[16];         // per-batch count of Nyquist-argmax features

// ---------------- f32x2 packed helpers --------------------------------------
__device__ __forceinline__ unsigned long long pk2(float x, float y) {
    unsigned long long r;
    asm("mov.b64 %0, {%1,%2};" : "=l"(r) : "f"(x), "f"(y));
    return r;
}
__device__ __forceinline__ float2 up2(unsigned long long v) {
    float2 r;
    asm("mov.b64 {%0,%1}, %2;" : "=f"(r.x), "=f"(r.y) : "l"(v));
    return r;
}
__device__ __forceinline__ unsigned long long fma2(unsigned long long a,
                                                   unsigned long long b,
                                                   unsigned long long c) {
    unsigned long long d;
    asm("fma.rn.f32x2 %0, %1, %2, %3;" : "=l"(d) : "l"(a), "l"(b), "l"(c));
    return d;
}
__device__ __forceinline__ unsigned long long mul2(unsigned long long a,
                                                   unsigned long long b) {
    unsigned long long d;
    asm("mul.rn.f32x2 %0, %1, %2;" : "=l"(d) : "l"(a), "l"(b));
    return d;
}

// ---------------- K0: build T, transpose conv_w, zero counts -----------------
// 512 blocks x 256 threads. Block r = table row r; thread j makes cols (2j,2j+1).
// Angle rounded to f32 (matching numpy's float32 pipeline), sin/cos in double.
__global__ void setup_kernel(const float* __restrict__ conv_w) {
    int r = blockIdx.x;
    int j = threadIdx.x;
    float divf = (float)exp((double)(-2 * j) * (log(10000.0) / 512.0));
    float angf = (float)r * divf;              // f32 product, like reference
    double ang = (double)angf;
    g_T[r * 512 + 2 * j]     = (float)sin(ang);
    g_T[r * 512 + 2 * j + 1] = (float)cos(ang);
    if (r == 0 && j < 16) g_cnt[j] = 0;
    if (r < 96) {
        int c = r & 31, tap = r >> 5;
        for (int d = j; d < 512; d += 256)
            g_Wt[r * 512 + d] = conv_w[d * 96 + c * 3 + tap];
    }
}

// ---------------- K1: DFT argmax flags ---------------------------------------
// 128 blocks: (b, group of 4 features). 256 threads = bins 0..255, one per thread.
// f32x2 packs (even t, odd t); z advances by w^2 each step. Nyquist bin exact.
__global__ void __launch_bounds__(256) dft_kernel(const float* __restrict__ x) {
    __shared__ float xs[4][514];
    __shared__ float red[4][256];
    int blk = blockIdx.x;
    int b = blk >> 3;
    int n0 = (blk & 7) * 4;

    for (int i = threadIdx.x; i < 4 * 512; i += 256) {
        int s = i & 3, t = i >> 2;
        xs[s][t] = x[(b * 512 + t) * 32 + n0 + s];
    }
    __syncthreads();

    int k = threadIdx.x;  // bin 0..255
    float s1, c1, s2, c2;
    sincospif(-(float)k * (1.0f / 256.0f), &s1, &c1);  // e^{-i 2pi k/512}
    sincospif(-(float)k * (1.0f / 128.0f), &s2, &c2);  // w^2
    unsigned long long zr = pk2(1.0f, c1);
    unsigned long long zi = pk2(0.0f, s1);
    unsigned long long wr = pk2(c2, c2);
    unsigned long long wi = pk2(s2, s2);
    unsigned long long nwi = pk2(-s2, -s2);
    unsigned long long ar[4], ai[4];
#pragma unroll
    for (int s = 0; s < 4; ++s) { ar[s] = 0ULL; ai[s] = 0ULL; }

#pragma unroll 4
    for (int t2 = 0; t2 < 256; ++t2) {
        unsigned long long x0 = *(const unsigned long long*)&xs[0][2 * t2];
        unsigned long long x1 = *(const unsigned long long*)&xs[1][2 * t2];
        unsigned long long x2 = *(const unsigned long long*)&xs[2][2 * t2];
        unsigned long long x3 = *(const unsigned long long*)&xs[3][2 * t2];
        ar[0] = fma2(x0, zr, ar[0]); ai[0] = fma2(x0, zi, ai[0]);
        ar[1] = fma2(x1, zr, ar[1]); ai[1] = fma2(x1, zi, ai[1]);
        ar[2] = fma2(x2, zr, ar[2]); ai[2] = fma2(x2, zi, ai[2]);
        ar[3] = fma2(x3, zr, ar[3]); ai[3] = fma2(x3, zi, ai[3]);
        unsigned long long t0m = mul2(zr, wr);
        unsigned long long t1m = mul2(zr, wi);
        zr = fma2(zi, nwi, t0m);
        zi = fma2(zi, wr, t1m);
    }
#pragma unroll
    for (int s = 0; s < 4; ++s) {
        float2 ur = up2(ar[s]);
        float2 ui = up2(ai[s]);
        float re = ur.x + ur.y;
        float im = ui.x + ui.y;
        red[s][k] = re * re + im * im;
    }
    __syncthreads();

    int wid = threadIdx.x >> 5, lane = threadIdx.x & 31;
    if (wid < 4) {
        int s = wid;
        // exact Nyquist: sum_t x[t]*(-1)^t  (lane parity == t parity)
        float acc = 0.0f;
#pragma unroll
        for (int j = 0; j < 16; ++j) acc += xs[s][lane + 32 * j];
        float v = (lane & 1) ? -acc : acc;
#pragma unroll
        for (int o = 16; o > 0; o >>= 1) v += __shfl_xor_sync(0xffffffffu, v, o);
        float nyq2 = v * v;
        float mx = 0.0f;
#pragma unroll
        for (int j = 0; j < 8; ++j) mx = fmaxf(mx, red[s][lane + 32 * j]);
#pragma unroll
        for (int o = 16; o > 0; o >>= 1)
            mx = fmaxf(mx, __shfl_xor_sync(0xffffffffu, mx, o));
        if (lane == 0 && nyq2 > mx) atomicAdd(&g_cnt[b], 1);
    }
}

// ---------------- K2: conv GEMM (f32x2) + fused epilogue ---------------------
// Tile: 64 t x 128 d per block, grid (4 d-tiles, 8 t-tiles, 16 b).
// 256 threads = 8 tx (d) x 32 ty (t); thread computes 2 t x 16 d.
#define XS_FLOATS 2180                    // 66*33 = 2178, padded to 16B multiple
#define WS_FLOATS (96 * 128)
#define SMEM_BYTES ((XS_FLOATS + WS_FLOATS) * 4)

extern __shared__ float smem2[];

__global__ void __launch_bounds__(256, 3)
main_kernel(const float* __restrict__ x, const int* __restrict__ xmark,
            float* __restrict__ out) {
    float* xs = smem2;                 // [66][33]: rows t0-1 .. t0+64
    float* Ws = smem2 + XS_FLOATS;     // [96][128]

    int b = blockIdx.z;
    int t0 = blockIdx.y * 64;
    int d0 = blockIdx.x * 128;
    int tid = threadIdx.x;
    int tx = tid & 7, ty = tid >> 3;

    for (int i = tid; i < 96 * 128; i += 256)
        Ws[i] = g_Wt[(i >> 7) * 512 + d0 + (i & 127)];

    const float* xb = x + b * (512 * 32);
    for (int i = tid; i < 66 * 32; i += 256) {
        int r = i >> 5, c = i & 31;
        xs[r * 33 + c] = xb[((t0 + r - 1) & 511) * 32 + c];
    }
    __syncthreads();

    unsigned long long acc[2][4][2];
#pragma unroll
    for (int dt = 0; dt < 2; ++dt)
#pragma unroll
        for (int j = 0; j < 4; ++j) { acc[dt][j][0] = 0ULL; acc[dt][j][1] = 0ULL; }

#pragma unroll
    for (int tap = 0; tap < 3; ++tap) {
        const float* ar0 = xs + (2 * ty + tap) * 33;
        const float* ar1 = ar0 + 33;
        const float* wbase = Ws + tap * 32 * 128 + tx * 4;
#pragma unroll 4
        for (int c = 0; c < 32; ++c) {
            float a0 = ar0[c];
            float a1 = ar1[c];
            unsigned long long a00 = pk2(a0, a0);
            unsigned long long a11 = pk2(a1, a1);
            const ulonglong2* wp = (const ulonglong2*)(wbase + c * 128);
#pragma unroll
            for (int j = 0; j < 4; ++j) {
                ulonglong2 wv = wp[j * 8];   // j*32 floats = 8 ulonglong2
                acc[0][j][0] = fma2(a00, wv.x, acc[0][j][0]);
                acc[0][j][1] = fma2(a00, wv.y, acc[0][j][1]);
                acc[1][j][0] = fma2(a11, wv.x, acc[1][j][0]);
                acc[1][j][1] = fma2(a11, wv.y, acc[1][j][1]);
            }
        }
    }

    // epilogue: + temporal (4 table rows) + cycle (a*T[t] + (1-a)*parity)
    int cnt = g_cnt[b];
    float af = (float)(32 - cnt) * (1.0f / 32.0f);
    float bf = (float)cnt * (1.0f / 32.0f);

#pragma unroll
    for (int dt = 0; dt < 2; ++dt) {
        int tg = t0 + 2 * ty + dt;
        int4 xm = *(const int4*)(xmark + (b * 512 + tg) * 4);
        int dbase = d0 + tx * 4;
        const float* Tm = g_T + xm.x * 512 + dbase;  // month
        const float* Td = g_T + xm.y * 512 + dbase;  // day
        const float* Tw = g_T + xm.z * 512 + dbase;  // weekday
        const float* Th = g_T + xm.w * 512 + dbase;  // hour
        const float* Tt = g_T + tg * 512 + dbase;    // cycle row
        float* op = out + (size_t)(b * 512 + tg) * 512 + dbase;
#pragma unroll
        for (int j = 0; j < 4; ++j) {
            int off = j * 32;
            float4 m4 = *(const float4*)(Tm + off);
            float4 d4 = *(const float4*)(Td + off);
            float4 w4 = *(const float4*)(Tw + off);
            float4 h4 = *(const float4*)(Th + off);
            float4 t4 = *(const float4*)(Tt + off);
            float2 p0 = up2(acc[dt][j][0]);
            float2 p1 = up2(acc[dt][j][1]);
            float4 r;
            r.x = p0.x + m4.x + d4.x + w4.x + h4.x + af * t4.x;
            r.y = p0.y + m4.y + d4.y + w4.y + h4.y + af * t4.y + bf;
            r.z = p1.x + m4.z + d4.z + w4.z + h4.z + af * t4.z;
            r.w = p1.y + m4.w + d4.w + w4.w + h4.w + af * t4.w + bf;
            *(float4*)(op + off) = r;
        }
    }
}

// ---------------- launch -----------------------------------------------------
extern "C" void kernel_launch(void* const* d_in, const int* in_sizes, int n_in,
                              void* d_out, int out_size) {
    const float* x      = (const float*)d_in[0];
    const int*   xmark  = (const int*)d_in[1];
    const float* conv_w = (const float*)d_in[2];
    float* out = (float*)d_out;

    cudaFuncSetAttribute(main_kernel, cudaFuncAttributeMaxDynamicSharedMemorySize,
                         SMEM_BYTES);

    setup_kernel<<<512, 256>>>(conv_w);
    dft_kernel<<<128, 256>>>(x);
    main_kernel<<<dim3(4, 8, 16), 256, SMEM_BYTES>>>(x, xmark, out);
}

// round 9
// speedup vs baseline: 1.3973x; 1.3973x over previous
#include <cuda_runtime.h>
#include <cuda_bf16.h>
#include <cstdint>
#include <math.h>

// ---------------- device scratch (no allocations allowed) -------------------
__device__ float g_T[512 * 512];    // fixed sinusoidal table, rows 0..511
__device__ float g_Wt[96 * 512];    // conv weight transposed: [kk = tap*32+c][d]
__device__ int   g_cnt[16];         // per-batch count of Nyquist-argmax features

// ---------------- f32x2 packed helpers --------------------------------------
__device__ __forceinline__ unsigned long long pk2(float x, float y) {
    unsigned long long r;
    asm("mov.b64 %0, {%1,%2};" : "=l"(r) : "f"(x), "f"(y));
    return r;
}
__device__ __forceinline__ float2 up2(unsigned long long v) {
    float2 r;
    asm("mov.b64 {%0,%1}, %2;" : "=f"(r.x), "=f"(r.y) : "l"(v));
    return r;
}
__device__ __forceinline__ unsigned long long fma2(unsigned long long a,
                                                   unsigned long long b,
                                                   unsigned long long c) {
    unsigned long long d;
    asm("fma.rn.f32x2 %0, %1, %2, %3;" : "=l"(d) : "l"(a), "l"(b), "l"(c));
    return d;
}
__device__ __forceinline__ unsigned long long mul2(unsigned long long a,
                                                   unsigned long long b) {
    unsigned long long d;
    asm("mul.rn.f32x2 %0, %1, %2;" : "=l"(d) : "l"(a), "l"(b));
    return d;
}

// ---------------- K0: build T, transpose conv_w, zero counts -----------------
// 512 blocks x 256 threads. Block r = table row r; thread j makes cols (2j,2j+1).
// All-float math: the reference numpy pipeline is float32 throughout, so fp64
// here was pure waste (fp64 transcendentals cost 27.5us on the R4 profile).
// sincosf (accurate path) keeps range-reduction error tiny for angles up to 511.
__global__ void setup_kernel(const float* __restrict__ conv_w) {
    int r = blockIdx.x;
    int j = threadIdx.x;
    // div = 10000^(-2j/512) = 2^(-2j * log2(10000)/512)
    float divf = exp2f((float)(-2 * j) * (13.2877123795494f / 512.0f));
    float ang = (float)r * divf;
    float s, c;
    sincosf(ang, &s, &c);
    g_T[r * 512 + 2 * j]     = s;
    g_T[r * 512 + 2 * j + 1] = c;
    if (r == 0 && j < 16) g_cnt[j] = 0;
    if (r < 96) {
        int cc = r & 31, tap = r >> 5;
        for (int d = j; d < 512; d += 256)
            g_Wt[r * 512 + d] = conv_w[d * 96 + cc * 3 + tap];
    }
}

// ---------------- K1: DFT argmax flags ---------------------------------------
// 128 blocks: (b, group of 4 features). 256 threads = bins 0..255, one per thread.
// f32x2 packs (even t, odd t); z advances by w^2 each step. Nyquist bin exact.
__global__ void __launch_bounds__(256) dft_kernel(const float* __restrict__ x) {
    __shared__ float xs[4][514];
    __shared__ float red[4][256];
    int blk = blockIdx.x;
    int b = blk >> 3;
    int n0 = (blk & 7) * 4;

    for (int i = threadIdx.x; i < 4 * 512; i += 256) {
        int s = i & 3, t = i >> 2;
        xs[s][t] = x[(b * 512 + t) * 32 + n0 + s];
    }
    __syncthreads();

    int k = threadIdx.x;  // bin 0..255
    float s1, c1, s2, c2;
    sincospif(-(float)k * (1.0f / 256.0f), &s1, &c1);  // e^{-i 2pi k/512}
    sincospif(-(float)k * (1.0f / 128.0f), &s2, &c2);  // w^2
    unsigned long long zr = pk2(1.0f, c1);
    unsigned long long zi = pk2(0.0f, s1);
    unsigned long long wr = pk2(c2, c2);
    unsigned long long wi = pk2(s2, s2);
    unsigned long long nwi = pk2(-s2, -s2);
    unsigned long long ar[4], ai[4];
#pragma unroll
    for (int s = 0; s < 4; ++s) { ar[s] = 0ULL; ai[s] = 0ULL; }

#pragma unroll 4
    for (int t2 = 0; t2 < 256; ++t2) {
        unsigned long long x0 = *(const unsigned long long*)&xs[0][2 * t2];
        unsigned long long x1 = *(const unsigned long long*)&xs[1][2 * t2];
        unsigned long long x2 = *(const unsigned long long*)&xs[2][2 * t2];
        unsigned long long x3 = *(const unsigned long long*)&xs[3][2 * t2];
        ar[0] = fma2(x0, zr, ar[0]); ai[0] = fma2(x0, zi, ai[0]);
        ar[1] = fma2(x1, zr, ar[1]); ai[1] = fma2(x1, zi, ai[1]);
        ar[2] = fma2(x2, zr, ar[2]); ai[2] = fma2(x2, zi, ai[2]);
        ar[3] = fma2(x3, zr, ar[3]); ai[3] = fma2(x3, zi, ai[3]);
        unsigned long long t0m = mul2(zr, wr);
        unsigned long long t1m = mul2(zr, wi);
        zr = fma2(zi, nwi, t0m);
        zi = fma2(zi, wr, t1m);
    }
#pragma unroll
    for (int s = 0; s < 4; ++s) {
        float2 ur = up2(ar[s]);
        float2 ui = up2(ai[s]);
        float re = ur.x + ur.y;
        float im = ui.x + ui.y;
        red[s][k] = re * re + im * im;
    }
    __syncthreads();

    int wid = threadIdx.x >> 5, lane = threadIdx.x & 31;
    if (wid < 4) {
        int s = wid;
        // exact Nyquist: sum_t x[t]*(-1)^t  (lane parity == t parity)
        float acc = 0.0f;
#pragma unroll
        for (int j = 0; j < 16; ++j) acc += xs[s][lane + 32 * j];
        float v = (lane & 1) ? -acc : acc;
#pragma unroll
        for (int o = 16; o > 0; o >>= 1) v += __shfl_xor_sync(0xffffffffu, v, o);
        float nyq2 = v * v;
        float mx = 0.0f;
#pragma unroll
        for (int j = 0; j < 8; ++j) mx = fmaxf(mx, red[s][lane + 32 * j]);
#pragma unroll
        for (int o = 16; o > 0; o >>= 1)
            mx = fmaxf(mx, __shfl_xor_sync(0xffffffffu, mx, o));
        if (lane == 0 && nyq2 > mx) atomicAdd(&g_cnt[b], 1);
    }
}

// ---------------- K2: conv GEMM (f32x2) + fused epilogue ---------------------
// Tile: 64 t x 128 d per block, grid (4 d-tiles, 8 t-tiles, 16 b).
// 256 threads = 8 tx (d) x 32 ty (t); thread computes 2 t x 16 d.
#define XS_FLOATS 2180                    // 66*33 = 2178, padded to 16B multiple
#define WS_FLOATS (96 * 128)
#define SMEM_BYTES ((XS_FLOATS + WS_FLOATS) * 4)

extern __shared__ float smem2[];

__global__ void __launch_bounds__(256, 3)
main_kernel(const float* __restrict__ x, const int* __restrict__ xmark,
            float* __restrict__ out) {
    float* xs = smem2;                 // [66][33]: rows t0-1 .. t0+64
    float* Ws = smem2 + XS_FLOATS;     // [96][128]

    int b = blockIdx.z;
    int t0 = blockIdx.y * 64;
    int d0 = blockIdx.x * 128;
    int tid = threadIdx.x;
    int tx = tid & 7, ty = tid >> 3;

    for (int i = tid; i < 96 * 128; i += 256)
        Ws[i] = g_Wt[(i >> 7) * 512 + d0 + (i & 127)];

    const float* xb = x + b * (512 * 32);
    for (int i = tid; i < 66 * 32; i += 256) {
        int r = i >> 5, c = i & 31;
        xs[r * 33 + c] = xb[((t0 + r - 1) & 511) * 32 + c];
    }
    __syncthreads();

    unsigned long long acc[2][4][2];
#pragma unroll
    for (int dt = 0; dt < 2; ++dt)
#pragma unroll
        for (int j = 0; j < 4; ++j) { acc[dt][j][0] = 0ULL; acc[dt][j][1] = 0ULL; }

#pragma unroll
    for (int tap = 0; tap < 3; ++tap) {
        const float* ar0 = xs + (2 * ty + tap) * 33;
        const float* ar1 = ar0 + 33;
        const float* wbase = Ws + tap * 32 * 128 + tx * 4;
#pragma unroll 4
        for (int c = 0; c < 32; ++c) {
            float a0 = ar0[c];
            float a1 = ar1[c];
            unsigned long long a00 = pk2(a0, a0);
            unsigned long long a11 = pk2(a1, a1);
            const ulonglong2* wp = (const ulonglong2*)(wbase + c * 128);
#pragma unroll
            for (int j = 0; j < 4; ++j) {
                ulonglong2 wv = wp[j * 8];   // j*32 floats = 8 ulonglong2
                acc[0][j][0] = fma2(a00, wv.x, acc[0][j][0]);
                acc[0][j][1] = fma2(a00, wv.y, acc[0][j][1]);
                acc[1][j][0] = fma2(a11, wv.x, acc[1][j][0]);
                acc[1][j][1] = fma2(a11, wv.y, acc[1][j][1]);
            }
        }
    }

    // epilogue: + temporal (4 table rows) + cycle (a*T[t] + (1-a)*parity)
    int cnt = g_cnt[b];
    float af = (float)(32 - cnt) * (1.0f / 32.0f);
    float bf = (float)cnt * (1.0f / 32.0f);

#pragma unroll
    for (int dt = 0; dt < 2; ++dt) {
        int tg = t0 + 2 * ty + dt;
        int4 xm = *(const int4*)(xmark + (b * 512 + tg) * 4);
        int dbase = d0 + tx * 4;
        const float* Tm = g_T + xm.x * 512 + dbase;  // month
        const float* Td = g_T + xm.y * 512 + dbase;  // day
        const float* Tw = g_T + xm.z * 512 + dbase;  // weekday
        const float* Th = g_T + xm.w * 512 + dbase;  // hour
        const float* Tt = g_T + tg * 512 + dbase;    // cycle row
        float* op = out + (size_t)(b * 512 + tg) * 512 + dbase;
#pragma unroll
        for (int j = 0; j < 4; ++j) {
            int off = j * 32;
            float4 m4 = *(const float4*)(Tm + off);
            float4 d4 = *(const float4*)(Td + off);
            float4 w4 = *(const float4*)(Tw + off);
            float4 h4 = *(const float4*)(Th + off);
            float4 t4 = *(const float4*)(Tt + off);
            float2 p0 = up2(acc[dt][j][0]);
            float2 p1 = up2(acc[dt][j][1]);
            float4 r;
            r.x = p0.x + m4.x + d4.x + w4.x + h4.x + af * t4.x;
            r.y = p0.y + m4.y + d4.y + w4.y + h4.y + af * t4.y + bf;
            r.z = p1.x + m4.z + d4.z + w4.z + h4.z + af * t4.z;
            r.w = p1.y + m4.w + d4.w + w4.w + h4.w + af * t4.w + bf;
            *(float4*)(op + off) = r;
        }
    }
}

// ---------------- launch -----------------------------------------------------
extern "C" void kernel_launch(void* const* d_in, const int* in_sizes, int n_in,
                              void* d_out, int out_size) {
    const float* x      = (const float*)d_in[0];
    const int*   xmark  = (const int*)d_in[1];
    const float* conv_w = (const float*)d_in[2];
    float* out = (float*)d_out;

    cudaFuncSetAttribute(main_kernel, cudaFuncAttributeMaxDynamicSharedMemorySize,
                         SMEM_BYTES);

    setup_kernel<<<512, 256>>>(conv_w);
    dft_kernel<<<128, 256>>>(x);
    main_kernel<<<dim3(4, 8, 16), 256, SMEM_BYTES>>>(x, xmark, out);
}